// round 6
// baseline (speedup 1.0000x reference)
#include <cuda_runtime.h>
#include <math_constants.h>

#define BB 16
#define HH 50
#define SS 256
#define DD 256
#define KK 32
#define SM1 (SS - 1)       // 255
#define TROWS 8            // rows per tile
#define TBYTES (TROWS * DD * 4)   // 8192
#define NTILES 32          // 32*8 = 256 slots (slot 255 is pad)
#define STAGES 4

__device__ __forceinline__ void cp_async16(unsigned smem_addr, const void* gptr) {
    asm volatile("cp.async.cg.shared.global [%0], [%1], 16;\n"
                 :: "r"(smem_addr), "l"(gptr));
}
__device__ __forceinline__ void cp_commit() {
    asm volatile("cp.async.commit_group;\n");
}
template<int N>
__device__ __forceinline__ void cp_wait() {
    asm volatile("cp.async.wait_group %0;\n" :: "n"(N));
}

__global__ __launch_bounds__(256, 6)
void matching_reducer_kernel(
    const float* __restrict__ sel,   // (B,H,S,D)
    const float* __restrict__ txt,   // (B,H,S,D)
    const float* __restrict__ user,  // (B,1,D)
    const float* __restrict__ am,    // (B,H,S)
    const int*   __restrict__ rm,    // (B,H,S)
    const float* __restrict__ seg,   // (H,1,D)
    float* __restrict__ out_terms,   // (B, H*K, D)
    float* __restrict__ out_mask,    // (B, H*K)
    float* __restrict__ out_kid)     // (B, H, K) as float
{
    const unsigned bh   = blockIdx.x;
    const unsigned b    = bh / HH;
    const unsigned h    = bh % HH;
    const unsigned tid  = threadIdx.x;   // 0..255
    const unsigned wid  = tid >> 5;      // 0..7
    const unsigned lane = tid & 31;

    __shared__ float buf[STAGES * TROWS * DD];   // 32 KB ring
    __shared__ float scores[SS];                 // slot s-1; [255] pad = -inf
    __shared__ int   srm[SS];
    __shared__ float sel_score[KK];
    __shared__ int   sel_idx[KK];
    __shared__ float sw[KK];
    __shared__ float wss[8];

    const unsigned buf_base = (unsigned)__cvta_generic_to_shared(buf);
    // sel byte region for this bh, starting at row 1
    const char* selrow1 = (const char*)(sel + (size_t)bh * SS * DD) + DD * 4;
    const unsigned max_src = (unsigned)(SM1 * DD * 4 - 16);  // clamp inside rows 1..255

    // ---- issue prologue tiles 0..STAGES-2 (one commit group per tile) ----
    #pragma unroll
    for (int t = 0; t < STAGES - 1; ++t) {
        unsigned dstb = buf_base + (unsigned)(t & (STAGES - 1)) * TBYTES;
        unsigned rel0 = (unsigned)t * TBYTES + tid * 16;
        #pragma unroll
        for (int j = 0; j < 2; ++j) {
            unsigned rel = rel0 + j * 4096;
            unsigned src = rel > max_src ? max_src : rel;
            cp_async16(dstb + tid * 16 + j * 4096, selrow1 + src);
        }
        cp_commit();
    }

    // ---- phase 1: stage rm; compute 1/||q|| ----
    srm[tid] = rm[bh * SS + tid];
    float qv = user[b * DD + tid];
    float ssq = qv * qv;
    #pragma unroll
    for (int o = 16; o; o >>= 1) ssq += __shfl_xor_sync(0xffffffffu, ssq, o);
    if (lane == 0) wss[wid] = ssq;
    __syncthreads();
    if (tid == 0) {
        float t = 0.f;
        #pragma unroll
        for (int i = 0; i < 8; i++) t += wss[i];
        wss[0] = 1.0f / fmaxf(sqrtf(t), 1e-12f);
    }
    __syncthreads();
    const float qscale = wss[0];
    const float4* u4 = reinterpret_cast<const float4*>(user + b * DD);
    float4 q0 = u4[lane];
    float4 q1 = u4[lane + 32];
    q0.x *= qscale; q0.y *= qscale; q0.z *= qscale; q0.w *= qscale;
    q1.x *= qscale; q1.y *= qscale; q1.z *= qscale; q1.w *= qscale;

    // ---- phase 2: pipelined scoring, one row per warp per tile ----
    // Invariant: exactly one commit group per tile index, INCLUDING empty
    // groups in the drain tail, so wait_group<2> always means "tile t landed".
    for (int t = 0; t < NTILES; ++t) {
        cp_wait<STAGES - 2>();       // tile t arrived
        __syncthreads();             // visible to all; buffer (t-1)%4 free

        // refill tile t+3 into the buffer computed at iter t-1 (or commit empty)
        if (t + STAGES - 1 < NTILES) {
            int tn = t + STAGES - 1;
            unsigned dstb = buf_base + (unsigned)(tn & (STAGES - 1)) * TBYTES;
            unsigned rel0 = (unsigned)tn * TBYTES + tid * 16;
            #pragma unroll
            for (int j = 0; j < 2; ++j) {
                unsigned rel = rel0 + j * 4096;
                unsigned src = rel > max_src ? max_src : rel;
                cp_async16(dstb + tid * 16 + j * 4096, selrow1 + src);
            }
        }
        cp_commit();                 // ALWAYS: keeps group count == tile count

        // compute: warp w owns slot = t*8 + w  (row s = slot+1)
        const int slot = t * TROWS + (int)wid;
        const float* rowp = buf + (size_t)(t & (STAGES - 1)) * TROWS * DD + wid * DD;
        const float4* r4 = reinterpret_cast<const float4*>(rowp);
        float4 a0 = r4[lane];
        float4 a1 = r4[lane + 32];
        float dot = a0.x*q0.x + a0.y*q0.y + a0.z*q0.z + a0.w*q0.w
                  + a1.x*q1.x + a1.y*q1.y + a1.z*q1.z + a1.w*q1.w;
        float sq  = a0.x*a0.x + a0.y*a0.y + a0.z*a0.z + a0.w*a0.w
                  + a1.x*a1.x + a1.y*a1.y + a1.z*a1.z + a1.w*a1.w;
        #pragma unroll
        for (int o = 16; o; o >>= 1) {
            dot += __shfl_xor_sync(0xffffffffu, dot, o);
            sq  += __shfl_xor_sync(0xffffffffu, sq,  o);
        }
        if (lane == 0) {
            if (slot >= SM1) {
                scores[slot] = -CUDART_INF_F;          // pad slot 255
            } else {
                float sc = dot / fmaxf(sqrtf(sq), 1e-12f);
                bool valid = (srm[slot + 1] != 0) || (slot < KK);
                scores[slot] = valid ? sc : -CUDART_INF_F;
            }
        }
    }
    __syncthreads();

    // ---- phase 3+4: barrier-free top-K + softmax in warp 0 ----
    if (wid == 0) {
        float v[8];
        #pragma unroll
        for (int j = 0; j < 8; ++j) v[j] = scores[lane * 8 + j];

        for (int k = 0; k < KK; ++k) {
            float bv = v[0]; int bj = 0;
            #pragma unroll
            for (int j = 1; j < 8; ++j)
                if (v[j] > bv) { bv = v[j]; bj = j; }
            int gi = lane * 8 + bj;
            #pragma unroll
            for (int o = 16; o; o >>= 1) {
                float ov = __shfl_xor_sync(0xffffffffu, bv, o);
                int   oi = __shfl_xor_sync(0xffffffffu, gi, o);
                if (ov > bv || (ov == bv && oi < gi)) { bv = ov; gi = oi; }
            }
            if (lane == 0) { sel_score[k] = bv; sel_idx[k] = gi; }
            if ((unsigned)(gi >> 3) == lane) v[gi & 7] = -CUDART_INF_F;
        }
        __syncwarp();
        float s = sel_score[lane];     // KK == 32
        float m = sel_score[0];        // descending -> max first
        float e = expf(s - m);
        float sum = e;
        #pragma unroll
        for (int o = 16; o; o >>= 1) sum += __shfl_xor_sync(0xffffffffu, sum, o);
        sw[lane] = e / sum;
    }
    __syncthreads();

    // ---- phase 5: gather + w*txt + seg (4 rows per warp) ----
    const float* txtbase = txt + (size_t)bh * SS * DD;
    const float* ambase  = am + bh * SS;
    float* terms = out_terms + (size_t)bh * KK * DD;
    const float4* sg = reinterpret_cast<const float4*>(seg + h * DD);
    const float4 g0 = sg[lane];
    const float4 g1 = sg[lane + 32];

    {
        const int k0 = (int)wid * 4;     // 8 warps * 4 = 32 = KK
        float4 a[4][2];
        float  w[4];
        #pragma unroll
        for (int u = 0; u < 4; ++u) {
            const int id = sel_idx[k0 + u];
            w[u] = sw[k0 + u];
            const float4* row = reinterpret_cast<const float4*>(
                txtbase + (size_t)(id + 1) * DD);
            a[u][0] = __ldcs(row + lane);
            a[u][1] = __ldcs(row + lane + 32);
        }
        #pragma unroll
        for (int u = 0; u < 4; ++u) {
            float4 a0 = a[u][0], a1 = a[u][1];
            float4 r0 = make_float4(fmaf(a0.x, w[u], g0.x), fmaf(a0.y, w[u], g0.y),
                                    fmaf(a0.z, w[u], g0.z), fmaf(a0.w, w[u], g0.w));
            float4 r1 = make_float4(fmaf(a1.x, w[u], g1.x), fmaf(a1.y, w[u], g1.y),
                                    fmaf(a1.z, w[u], g1.z), fmaf(a1.w, w[u], g1.w));
            float4* orow = reinterpret_cast<float4*>(terms + (unsigned)(k0 + u) * DD);
            orow[lane]      = r0;
            orow[lane + 32] = r1;
        }
    }

    if (tid < KK) {
        int id = sel_idx[tid];
        out_mask[bh * KK + tid] = ambase[id + 1];
        out_kid [bh * KK + tid] = (float)id;
    }
}

extern "C" void kernel_launch(void* const* d_in, const int* in_sizes, int n_in,
                              void* d_out, int out_size) {
    const float* sel  = (const float*)d_in[0];
    const float* txt  = (const float*)d_in[1];
    const float* user = (const float*)d_in[2];
    // d_in[3] = news_repr (unused)
    const float* am   = (const float*)d_in[4];
    const int*   rm   = (const int*)  d_in[5];
    const float* seg  = (const float*)d_in[6];

    float* out = (float*)d_out;
    const size_t terms_elems = (size_t)BB * HH * KK * DD;
    const size_t mask_elems  = (size_t)BB * HH * KK;
    float* out_terms = out;
    float* out_mask  = out + terms_elems;
    float* out_kid   = out + terms_elems + mask_elems;

    matching_reducer_kernel<<<BB * HH, 256>>>(sel, txt, user, am, rm, seg,
                                              out_terms, out_mask, out_kid);
}